// round 1
// baseline (speedup 1.0000x reference)
#include <cuda_runtime.h>
#include <cstdint>

// ---------------- problem constants ----------------
#define BATCH   32
#define HH      56
#define WW      56
#define CC      256
#define HEADS   8
#define HD      32
#define WIN     7
#define SHIFT   3
#define NN      49                  // WIN*WIN
#define NWIN    64                  // (56/7)^2 windows per image
#define NWTOT   (BATCH * NWIN)      // 2048
#define MTOT    (NWTOT * NN)        // 100352 rows

// ---------------- scratch (device globals; no alloc allowed) ----------------
__device__ float g_qkv[(size_t)MTOT * 768];   // [m, 3*C]  (3, heads, hd) packing
__device__ float g_att[(size_t)MTOT * 256];   // [m, C]    'wnhd' flattened

// Map a flattened window-row index m -> element offset of the source pixel in x.
// Window partition is of the shifted image xs[i] = x[(i+3)%56]; the output scatter
// uses the SAME map because roll(+3) inverts roll(-3).
__device__ __forceinline__ int src_offset(int m) {
    int wq = m / NN;
    int n  = m - wq * NN;
    int b  = wq >> 6;
    int wi = wq & 63;
    int wh = wi >> 3, ww = wi & 7;
    int r = wh * WIN + n / WIN;
    int c = ww * WIN + n % WIN;
    int sh = r + SHIFT; if (sh >= HH) sh -= HH;
    int sw = c + SHIFT; if (sw >= WW) sw -= WW;
    return ((b * HH + sh) * WW + sw) * CC;
}

// =====================================================================
// Kernel 1: QKV GEMM, fused shifted-window gather.
//   g_qkv[m, o] = sum_k x_gathered[m,k] * qkv_w[o,k] + qkv_b[o]
// Tiles: BM=64, BN=64, BK=16, 256 threads, 4x4 microtile.
// =====================================================================
__global__ __launch_bounds__(256) void qkv_gemm(const float* __restrict__ x,
                                                const float* __restrict__ w,
                                                const float* __restrict__ bias) {
    __shared__ float As[16][68];   // [k][m], padded (+4) to kill store conflicts
    __shared__ float Bs[16][68];   // [k][o]
    __shared__ int rowoff[64];

    const int n0 = blockIdx.x * 64;          // N (output-col) tile in .x -> A reuse in L2
    const int m0 = blockIdx.y * 64;
    const int t  = threadIdx.x;

    if (t < 64) rowoff[t] = src_offset(m0 + t);
    __syncthreads();

    const int ml = t >> 2, kq = t & 3;
    const int tx = t & 15, ty = t >> 4;

    const float* arow = x + rowoff[ml] + kq * 4;
    const float* brow = w + (n0 + ml) * CC + kq * 4;

    float acc[4][4];
#pragma unroll
    for (int i = 0; i < 4; i++)
#pragma unroll
        for (int j = 0; j < 4; j++) acc[i][j] = 0.f;

    for (int k0 = 0; k0 < CC; k0 += 16) {
        float4 a4 = *(const float4*)(arow + k0);
        float4 b4 = *(const float4*)(brow + k0);
        As[kq * 4 + 0][ml] = a4.x; As[kq * 4 + 1][ml] = a4.y;
        As[kq * 4 + 2][ml] = a4.z; As[kq * 4 + 3][ml] = a4.w;
        Bs[kq * 4 + 0][ml] = b4.x; Bs[kq * 4 + 1][ml] = b4.y;
        Bs[kq * 4 + 2][ml] = b4.z; Bs[kq * 4 + 3][ml] = b4.w;
        __syncthreads();
#pragma unroll
        for (int k = 0; k < 16; k++) {
            float4 av = *(const float4*)&As[k][ty * 4];
            float4 bv = *(const float4*)&Bs[k][tx * 4];
            acc[0][0] += av.x * bv.x; acc[0][1] += av.x * bv.y;
            acc[0][2] += av.x * bv.z; acc[0][3] += av.x * bv.w;
            acc[1][0] += av.y * bv.x; acc[1][1] += av.y * bv.y;
            acc[1][2] += av.y * bv.z; acc[1][3] += av.y * bv.w;
            acc[2][0] += av.z * bv.x; acc[2][1] += av.z * bv.y;
            acc[2][2] += av.z * bv.z; acc[2][3] += av.z * bv.w;
            acc[3][0] += av.w * bv.x; acc[3][1] += av.w * bv.y;
            acc[3][2] += av.w * bv.z; acc[3][3] += av.w * bv.w;
        }
        __syncthreads();
    }

    float4 bb = *(const float4*)(bias + n0 + tx * 4);
#pragma unroll
    for (int i = 0; i < 4; i++) {
        float4 o;
        o.x = acc[i][0] + bb.x; o.y = acc[i][1] + bb.y;
        o.z = acc[i][2] + bb.z; o.w = acc[i][3] + bb.w;
        *(float4*)(g_qkv + (size_t)(m0 + ty * 4 + i) * 768 + n0 + tx * 4) = o;
    }
}

// =====================================================================
// Kernel 2: windowed attention. One block per (window, head).
//   S = (q kT) * hd^-0.5 + rel_bias + shift_mask ; P = softmax(S) ; out = P v
// =====================================================================
__global__ __launch_bounds__(256) void attn_kernel(const float* __restrict__ tbl,
                                                   const int* __restrict__ relidx) {
    __shared__ float qs[NN * HD];        // [i][d]
    __shared__ float vs[NN * HD];        // [j][d]
    __shared__ float kT[HD * 56];        // [d][j], row stride 56 (conflict-free vs j)
    __shared__ float sS[NN * 52];        // scores, row stride 52
    __shared__ float tbs[169];           // bias table column for this head
    __shared__ int   ris[NN * NN];       // rel_index
    __shared__ int   rgn[NN];            // shift-mask region label per window element

    const int w = blockIdx.x >> 3;
    const int h = blockIdx.x & 7;
    const int t = threadIdx.x;

    const float* base = g_qkv + (size_t)w * NN * 768 + h * HD;
    for (int idx = t; idx < NN * 8; idx += 256) {       // 49 rows x 8 float4
        int n = idx >> 3, dq = idx & 7;
        const float4* p = (const float4*)(base + n * 768 + dq * 4);
        float4 q4 = p[0];       // q at +0
        float4 k4 = p[64];      // k at +256 floats
        float4 v4 = p[128];     // v at +512 floats
        *(float4*)&qs[n * HD + dq * 4] = q4;
        *(float4*)&vs[n * HD + dq * 4] = v4;
        kT[(dq * 4 + 0) * 56 + n] = k4.x;
        kT[(dq * 4 + 1) * 56 + n] = k4.y;
        kT[(dq * 4 + 2) * 56 + n] = k4.z;
        kT[(dq * 4 + 3) * 56 + n] = k4.w;
    }
    for (int idx = t; idx < NN * NN; idx += 256) ris[idx] = relidx[idx];
    if (t < 169) tbs[t] = tbl[t * HEADS + h];
    if (t < NN) {
        int wi = w & 63, wh = wi >> 3, ww = wi & 7;
        int r = wh * WIN + t / WIN;
        int c = ww * WIN + t % WIN;
        int rh = (r < HH - WIN) ? 0 : ((r < HH - SHIFT) ? 1 : 2);
        int rw = (c < WW - WIN) ? 0 : ((c < WW - SHIFT) ? 1 : 2);
        rgn[t] = rh * 3 + rw;
    }
    __syncthreads();

    // ---- scores: 4 row-groups x 64 j-lanes ----
    const int jg = t & 63, rgp = t >> 6;
    const float scale = 0.17677669529663687f;   // 32^-0.5
    for (int i = rgp; i < NN; i += 4) {
        if (jg < NN) {
            float acc = 0.f;
#pragma unroll
            for (int kk = 0; kk < HD; kk++)
                acc += qs[i * HD + kk] * kT[kk * 56 + jg];   // q broadcast, kT stride-1
            float bia = tbs[ris[i * NN + jg]];
            float msk = (rgn[i] == rgn[jg]) ? 0.f : -100.f;
            sS[i * 52 + jg] = acc * scale + bia + msk;
        }
    }
    __syncthreads();

    // ---- softmax: one warp per row ----
    const int wid = t >> 5, lane = t & 31;
    for (int i = wid; i < NN; i += 8) {
        float e0 = sS[i * 52 + lane];
        float e1 = (lane + 32 < NN) ? sS[i * 52 + lane + 32] : -1e30f;
        float mx = fmaxf(e0, e1);
#pragma unroll
        for (int o = 16; o; o >>= 1) mx = fmaxf(mx, __shfl_xor_sync(0xffffffffu, mx, o));
        e0 = __expf(e0 - mx);
        e1 = (lane + 32 < NN) ? __expf(e1 - mx) : 0.f;
        float sm = e0 + e1;
#pragma unroll
        for (int o = 16; o; o >>= 1) sm += __shfl_xor_sync(0xffffffffu, sm, o);
        float inv = 1.f / sm;
        sS[i * 52 + lane] = e0 * inv;
        if (lane + 32 < NN) sS[i * 52 + lane + 32] = e1 * inv;
    }
    __syncthreads();

    // ---- P @ V: 8 row-groups x 32 d-lanes ----
    const int d = t & 31, ig = t >> 5;
    float* outp = g_att + (size_t)w * NN * 256 + h * HD + d;
    for (int i = ig; i < NN; i += 8) {
        float acc = 0.f;
#pragma unroll
        for (int j = 0; j < NN; j++)
            acc += sS[i * 52 + j] * vs[j * HD + d];          // P broadcast, V stride-1
        outp[i * 256] = acc;
    }
}

// =====================================================================
// Kernel 3: proj GEMM, fused inverse-window + inverse-shift scatter.
//   out[pixel(m), o] = sum_k g_att[m,k] * proj_w[o,k] + proj_b[o]
// =====================================================================
__global__ __launch_bounds__(256) void proj_gemm(const float* __restrict__ w,
                                                 const float* __restrict__ bias,
                                                 float* __restrict__ out) {
    __shared__ float As[16][68];
    __shared__ float Bs[16][68];
    __shared__ int outoff[64];

    const int n0 = blockIdx.x * 64;
    const int m0 = blockIdx.y * 64;
    const int t  = threadIdx.x;

    if (t < 64) outoff[t] = src_offset(m0 + t);   // same bijection as the gather
    __syncthreads();

    const int ml = t >> 2, kq = t & 3;
    const int tx = t & 15, ty = t >> 4;

    const float* arow = g_att + (size_t)(m0 + ml) * 256 + kq * 4;
    const float* brow = w + (n0 + ml) * CC + kq * 4;

    float acc[4][4];
#pragma unroll
    for (int i = 0; i < 4; i++)
#pragma unroll
        for (int j = 0; j < 4; j++) acc[i][j] = 0.f;

    for (int k0 = 0; k0 < CC; k0 += 16) {
        float4 a4 = *(const float4*)(arow + k0);
        float4 b4 = *(const float4*)(brow + k0);
        As[kq * 4 + 0][ml] = a4.x; As[kq * 4 + 1][ml] = a4.y;
        As[kq * 4 + 2][ml] = a4.z; As[kq * 4 + 3][ml] = a4.w;
        Bs[kq * 4 + 0][ml] = b4.x; Bs[kq * 4 + 1][ml] = b4.y;
        Bs[kq * 4 + 2][ml] = b4.z; Bs[kq * 4 + 3][ml] = b4.w;
        __syncthreads();
#pragma unroll
        for (int k = 0; k < 16; k++) {
            float4 av = *(const float4*)&As[k][ty * 4];
            float4 bv = *(const float4*)&Bs[k][tx * 4];
            acc[0][0] += av.x * bv.x; acc[0][1] += av.x * bv.y;
            acc[0][2] += av.x * bv.z; acc[0][3] += av.x * bv.w;
            acc[1][0] += av.y * bv.x; acc[1][1] += av.y * bv.y;
            acc[1][2] += av.y * bv.z; acc[1][3] += av.y * bv.w;
            acc[2][0] += av.z * bv.x; acc[2][1] += av.z * bv.y;
            acc[2][2] += av.z * bv.z; acc[2][3] += av.z * bv.w;
            acc[3][0] += av.w * bv.x; acc[3][1] += av.w * bv.y;
            acc[3][2] += av.w * bv.z; acc[3][3] += av.w * bv.w;
        }
        __syncthreads();
    }

    float4 bb = *(const float4*)(bias + n0 + tx * 4);
#pragma unroll
    for (int i = 0; i < 4; i++) {
        float4 o;
        o.x = acc[i][0] + bb.x; o.y = acc[i][1] + bb.y;
        o.z = acc[i][2] + bb.z; o.w = acc[i][3] + bb.w;
        *(float4*)(out + outoff[ty * 4 + i] + n0 + tx * 4) = o;
    }
}

// =====================================================================
extern "C" void kernel_launch(void* const* d_in, const int* in_sizes, int n_in,
                              void* d_out, int out_size) {
    const float* x     = (const float*)d_in[0];
    const float* qkvw  = (const float*)d_in[1];
    const float* qkvb  = (const float*)d_in[2];
    const float* projw = (const float*)d_in[3];
    const float* projb = (const float*)d_in[4];
    const float* tbl   = (const float*)d_in[5];
    const int*   ridx  = (const int*)d_in[6];
    float* out = (float*)d_out;

    (void)in_sizes; (void)n_in; (void)out_size;

    // QKV: M=100352 (1568 tiles of 64), N=768 (12 tiles). N in .x for L2 reuse of x.
    qkv_gemm<<<dim3(12, MTOT / 64), 256>>>(x, qkvw, qkvb);
    // Attention: one block per (window, head)
    attn_kernel<<<NWTOT * HEADS, 256>>>(tbl, ridx);
    // Proj: N=256 (4 tiles)
    proj_gemm<<<dim3(4, MTOT / 64), 256>>>(projw, projb, out);
}

// round 3
// speedup vs baseline: 1.1968x; 1.1968x over previous
#include <cuda_runtime.h>
#include <cstdint>

// ---------------- problem constants ----------------
#define BATCH   32
#define HH      56
#define WW      56
#define CC      256
#define HEADS   8
#define HD      32
#define WIN     7
#define SHIFT   3
#define NN      49                  // WIN*WIN
#define NWIN    64                  // (56/7)^2 windows per image
#define NWTOT   (BATCH * NWIN)      // 2048
#define MTOT    (NWTOT * NN)        // 100352 rows

// ---------------- scratch (device globals; no alloc allowed) ----------------
// NOTE: referenced ONLY from device code. Passing these as kernel args from
// host code is UB (host-side symbol value is not a device pointer) — that
// was the Round-2 crash.
__device__ float g_qkv[(size_t)MTOT * 768];   // [m, 3*C]  (3, heads, hd) packing
__device__ float g_att[(size_t)MTOT * 256];   // [m, C]    'wnhd' flattened

// Map a flattened window-row index m -> element offset of the source pixel in x.
// Window partition is of the shifted image xs[i] = x[(i+3)%56]; the output scatter
// uses the SAME map because roll(+3) inverts roll(-3).
__device__ __forceinline__ int src_offset(int m) {
    int wq = m / NN;
    int n  = m - wq * NN;
    int b  = wq >> 6;
    int wi = wq & 63;
    int wh = wi >> 3, ww = wi & 7;
    int r = wh * WIN + n / WIN;
    int c = ww * WIN + n % WIN;
    int sh = r + SHIFT; if (sh >= HH) sh -= HH;
    int sw = c + SHIFT; if (sw >= WW) sw -= WW;
    return ((b * HH + sh) * WW + sw) * CC;
}

// =====================================================================
// 128x128x16 SGEMM, 256 threads, 8x8 microtile, double-buffered smem.
//   QKV=true : A = X (gathered via src_offset), C = g_qkv (device global, ldc=768)
//   QKV=false: A = g_att (device global, lda=256), C = OUT (scattered)
// C[m, n0+n] = sum_k A[m,k] * W[n0+n,k] + bias[n0+n]
// =====================================================================
template<bool QKV>
__global__ __launch_bounds__(256) void gemm128(const float* __restrict__ X,
                                               const float* __restrict__ W,
                                               const float* __restrict__ bias,
                                               float* __restrict__ OUT) {
    __shared__ float As[2][16][132];   // [buf][k][m], pad 132 (16B-multiple row)
    __shared__ float Bs[2][16][132];   // [buf][k][n]
    __shared__ int so[128];

    const int n0 = blockIdx.x * 128;   // N-tile in .x -> A rows reused across x in L2
    const int m0 = blockIdx.y * 128;
    const int t  = threadIdx.x;

    if (t < 128) so[t] = src_offset(m0 + t);
    __syncthreads();

    // ---- load mapping: r = row-in-tile halves, kq = k-quarter (float4) ----
    const int r  = t >> 2;            // 0..63
    const int kq = t & 3;             // 0..3

    const float* ap0;
    const float* ap1;
    if (QKV) {
        ap0 = X + so[r]      + kq * 4;
        ap1 = X + so[r + 64] + kq * 4;
    } else {
        ap0 = g_att + (size_t)(m0 + r)      * 256 + kq * 4;
        ap1 = g_att + (size_t)(m0 + r + 64) * 256 + kq * 4;
    }
    const float* bp0 = W + (size_t)(n0 + r)      * CC + kq * 4;
    const float* bp1 = W + (size_t)(n0 + r + 64) * CC + kq * 4;

    // ---- compute mapping ----
    const int tx = t & 15;            // n micro (8 cols each)
    const int ty = t >> 4;            // m micro (8 rows each)

    float acc[8][8];
#pragma unroll
    for (int i = 0; i < 8; i++)
#pragma unroll
        for (int j = 0; j < 8; j++) acc[i][j] = 0.f;

    // ---- prologue: tile 0 ----
    float4 ra0 = *(const float4*)ap0;
    float4 ra1 = *(const float4*)ap1;
    float4 rb0 = *(const float4*)bp0;
    float4 rb1 = *(const float4*)bp1;

    int buf = 0;
    {
        As[0][kq * 4 + 0][r] = ra0.x; As[0][kq * 4 + 1][r] = ra0.y;
        As[0][kq * 4 + 2][r] = ra0.z; As[0][kq * 4 + 3][r] = ra0.w;
        As[0][kq * 4 + 0][r + 64] = ra1.x; As[0][kq * 4 + 1][r + 64] = ra1.y;
        As[0][kq * 4 + 2][r + 64] = ra1.z; As[0][kq * 4 + 3][r + 64] = ra1.w;
        Bs[0][kq * 4 + 0][r] = rb0.x; Bs[0][kq * 4 + 1][r] = rb0.y;
        Bs[0][kq * 4 + 2][r] = rb0.z; Bs[0][kq * 4 + 3][r] = rb0.w;
        Bs[0][kq * 4 + 0][r + 64] = rb1.x; Bs[0][kq * 4 + 1][r + 64] = rb1.y;
        Bs[0][kq * 4 + 2][r + 64] = rb1.z; Bs[0][kq * 4 + 3][r + 64] = rb1.w;
    }
    __syncthreads();

#pragma unroll 1
    for (int it = 0; it < 16; ++it) {
        // prefetch next tile into registers (overlaps with FFMA block below)
        if (it < 15) {
            const int k0 = (it + 1) * 16;
            ra0 = *(const float4*)(ap0 + k0);
            ra1 = *(const float4*)(ap1 + k0);
            rb0 = *(const float4*)(bp0 + k0);
            rb1 = *(const float4*)(bp1 + k0);
        }

        // compute 16 k-steps from current buffer
#pragma unroll
        for (int k = 0; k < 16; k++) {
            float4 av0 = *(const float4*)&As[buf][k][ty * 8];
            float4 av1 = *(const float4*)&As[buf][k][ty * 8 + 4];
            float4 bv0 = *(const float4*)&Bs[buf][k][tx * 8];
            float4 bv1 = *(const float4*)&Bs[buf][k][tx * 8 + 4];
            float a[8] = {av0.x, av0.y, av0.z, av0.w, av1.x, av1.y, av1.z, av1.w};
            float b[8] = {bv0.x, bv0.y, bv0.z, bv0.w, bv1.x, bv1.y, bv1.z, bv1.w};
#pragma unroll
            for (int i = 0; i < 8; i++)
#pragma unroll
                for (int j = 0; j < 8; j++) acc[i][j] += a[i] * b[j];
        }

        if (it < 15) {
            const int nb = buf ^ 1;
            As[nb][kq * 4 + 0][r] = ra0.x; As[nb][kq * 4 + 1][r] = ra0.y;
            As[nb][kq * 4 + 2][r] = ra0.z; As[nb][kq * 4 + 3][r] = ra0.w;
            As[nb][kq * 4 + 0][r + 64] = ra1.x; As[nb][kq * 4 + 1][r + 64] = ra1.y;
            As[nb][kq * 4 + 2][r + 64] = ra1.z; As[nb][kq * 4 + 3][r + 64] = ra1.w;
            Bs[nb][kq * 4 + 0][r] = rb0.x; Bs[nb][kq * 4 + 1][r] = rb0.y;
            Bs[nb][kq * 4 + 2][r] = rb0.z; Bs[nb][kq * 4 + 3][r] = rb0.w;
            Bs[nb][kq * 4 + 0][r + 64] = rb1.x; Bs[nb][kq * 4 + 1][r + 64] = rb1.y;
            Bs[nb][kq * 4 + 2][r + 64] = rb1.z; Bs[nb][kq * 4 + 3][r + 64] = rb1.w;
            __syncthreads();
            buf = nb;
        }
    }

    // ---- epilogue ----
    float4 bb0 = *(const float4*)(bias + n0 + tx * 8);
    float4 bb1 = *(const float4*)(bias + n0 + tx * 8 + 4);
#pragma unroll
    for (int i = 0; i < 8; i++) {
        const int mr = ty * 8 + i;
        float* cp;
        if (QKV) cp = g_qkv + (size_t)(m0 + mr) * 768 + n0 + tx * 8;
        else     cp = OUT + so[mr] + n0 + tx * 8;
        float4 o0, o1;
        o0.x = acc[i][0] + bb0.x; o0.y = acc[i][1] + bb0.y;
        o0.z = acc[i][2] + bb0.z; o0.w = acc[i][3] + bb0.w;
        o1.x = acc[i][4] + bb1.x; o1.y = acc[i][5] + bb1.y;
        o1.z = acc[i][6] + bb1.z; o1.w = acc[i][7] + bb1.w;
        *(float4*)cp       = o0;
        *(float4*)(cp + 4) = o1;
    }
}

// =====================================================================
// Kernel 2: windowed attention. One block per (window, head).
//   S = (q kT) * hd^-0.5 + rel_bias + shift_mask ; P = softmax(S) ; out = P v
// =====================================================================
__global__ __launch_bounds__(256) void attn_kernel(const float* __restrict__ tbl,
                                                   const int* __restrict__ relidx) {
    __shared__ float qs[NN * HD];        // [i][d]
    __shared__ float vs[NN * HD];        // [j][d]
    __shared__ float kT[HD * 56];        // [d][j], row stride 56 (conflict-free vs j)
    __shared__ float sS[NN * 52];        // scores, row stride 52
    __shared__ float tbs[169];           // bias table column for this head
    __shared__ int   ris[NN * NN];       // rel_index
    __shared__ int   rgn[NN];            // shift-mask region label per window element

    const int w = blockIdx.x >> 3;
    const int h = blockIdx.x & 7;
    const int t = threadIdx.x;

    const float* base = g_qkv + (size_t)w * NN * 768 + h * HD;
    for (int idx = t; idx < NN * 8; idx += 256) {       // 49 rows x 8 float4
        int n = idx >> 3, dq = idx & 7;
        const float4* p = (const float4*)(base + n * 768 + dq * 4);
        float4 q4 = p[0];       // q at +0
        float4 k4 = p[64];      // k at +256 floats
        float4 v4 = p[128];     // v at +512 floats
        *(float4*)&qs[n * HD + dq * 4] = q4;
        *(float4*)&vs[n * HD + dq * 4] = v4;
        kT[(dq * 4 + 0) * 56 + n] = k4.x;
        kT[(dq * 4 + 1) * 56 + n] = k4.y;
        kT[(dq * 4 + 2) * 56 + n] = k4.z;
        kT[(dq * 4 + 3) * 56 + n] = k4.w;
    }
    for (int idx = t; idx < NN * NN; idx += 256) ris[idx] = relidx[idx];
    if (t < 169) tbs[t] = tbl[t * HEADS + h];
    if (t < NN) {
        int wi = w & 63, wh = wi >> 3, ww = wi & 7;
        int r = wh * WIN + t / WIN;
        int c = ww * WIN + t % WIN;
        int rh = (r < HH - WIN) ? 0 : ((r < HH - SHIFT) ? 1 : 2);
        int rw = (c < WW - WIN) ? 0 : ((c < WW - SHIFT) ? 1 : 2);
        rgn[t] = rh * 3 + rw;
    }
    __syncthreads();

    // ---- scores: 4 row-groups x 64 j-lanes ----
    const int jg = t & 63, rgp = t >> 6;
    const float scale = 0.17677669529663687f;   // 32^-0.5
    for (int i = rgp; i < NN; i += 4) {
        if (jg < NN) {
            float acc = 0.f;
#pragma unroll
            for (int kk = 0; kk < HD; kk++)
                acc += qs[i * HD + kk] * kT[kk * 56 + jg];   // q broadcast, kT stride-1
            float bia = tbs[ris[i * NN + jg]];
            float msk = (rgn[i] == rgn[jg]) ? 0.f : -100.f;
            sS[i * 52 + jg] = acc * scale + bia + msk;
        }
    }
    __syncthreads();

    // ---- softmax: one warp per row ----
    const int wid = t >> 5, lane = t & 31;
    for (int i = wid; i < NN; i += 8) {
        float e0 = sS[i * 52 + lane];
        float e1 = (lane + 32 < NN) ? sS[i * 52 + lane + 32] : -1e30f;
        float mx = fmaxf(e0, e1);
#pragma unroll
        for (int o = 16; o; o >>= 1) mx = fmaxf(mx, __shfl_xor_sync(0xffffffffu, mx, o));
        e0 = __expf(e0 - mx);
        e1 = (lane + 32 < NN) ? __expf(e1 - mx) : 0.f;
        float sm = e0 + e1;
#pragma unroll
        for (int o = 16; o; o >>= 1) sm += __shfl_xor_sync(0xffffffffu, sm, o);
        float inv = 1.f / sm;
        sS[i * 52 + lane] = e0 * inv;
        if (lane + 32 < NN) sS[i * 52 + lane + 32] = e1 * inv;
    }
    __syncthreads();

    // ---- P @ V: 8 row-groups x 32 d-lanes ----
    const int d = t & 31, ig = t >> 5;
    float* outp = g_att + (size_t)w * NN * 256 + h * HD + d;
    for (int i = ig; i < NN; i += 8) {
        float acc = 0.f;
#pragma unroll
        for (int j = 0; j < NN; j++)
            acc += sS[i * 52 + j] * vs[j * HD + d];          // P broadcast, V stride-1
        outp[i * 256] = acc;
    }
}

// =====================================================================
extern "C" void kernel_launch(void* const* d_in, const int* in_sizes, int n_in,
                              void* d_out, int out_size) {
    const float* x     = (const float*)d_in[0];
    const float* qkvw  = (const float*)d_in[1];
    const float* qkvb  = (const float*)d_in[2];
    const float* projw = (const float*)d_in[3];
    const float* projb = (const float*)d_in[4];
    const float* tbl   = (const float*)d_in[5];
    const int*   ridx  = (const int*)d_in[6];
    float* out = (float*)d_out;

    (void)in_sizes; (void)n_in; (void)out_size;

    // QKV: M=100352 (784 tiles of 128), N=768 (6 tiles). N in .x for L2 reuse of x.
    gemm128<true><<<dim3(6, MTOT / 128), 256>>>(x, qkvw, qkvb, nullptr);
    // Attention: one block per (window, head)
    attn_kernel<<<NWTOT * HEADS, 256>>>(tbl, ridx);
    // Proj: N=256 (2 tiles), fused inverse shift/window scatter
    gemm128<false><<<dim3(2, MTOT / 128), 256>>>(nullptr, projw, projb, out);
}

// round 4
// speedup vs baseline: 1.2663x; 1.0580x over previous
#include <cuda_runtime.h>
#include <cstdint>

// ---------------- problem constants ----------------
#define BATCH   32
#define HH      56
#define WW      56
#define CC      256
#define HEADS   8
#define HD      32
#define WIN     7
#define SHIFT   3
#define NN      49                  // WIN*WIN
#define NWIN    64                  // (56/7)^2 windows per image
#define NWTOT   (BATCH * NWIN)      // 2048
#define MTOT    (NWTOT * NN)        // 100352 rows

// ---------------- scratch (device globals; device-code refs only) ----------------
__device__ float g_qkv[(size_t)MTOT * 768];   // [m, 3*C]
__device__ float g_att[(size_t)MTOT * 256];   // [m, C] 'wnhd'
__device__ float g_bias[4 * HEADS * NN * 52]; // fused rel_bias + shift mask, 4 window classes

// Map a flattened window-row index m -> element offset of the source pixel in x.
// roll(+3) inverts roll(-3), so the same map serves gather (QKV) and scatter (proj).
__device__ __forceinline__ int src_offset(int m) {
    int wq = m / NN;
    int n  = m - wq * NN;
    int b  = wq >> 6;
    int wi = wq & 63;
    int wh = wi >> 3, ww = wi & 7;
    int r = wh * WIN + n / WIN;
    int c = ww * WIN + n % WIN;
    int sh = r + SHIFT; if (sh >= HH) sh -= HH;
    int sw = c + SHIFT; if (sw >= WW) sw -= WW;
    return ((b * HH + sh) * WW + sw) * CC;
}

// =====================================================================
// Kernel 0: fused bias+mask table. 4 classes x 8 heads.
//   mask depends only on (wh==7, ww==7) -> class = 2*(wh==7) + (ww==7)
// =====================================================================
__global__ void bias_kernel(const float* __restrict__ tbl,
                            const int* __restrict__ relidx) {
    const int cls = blockIdx.x & 3;
    const int h   = blockIdx.x >> 2;
    for (int idx = threadIdx.x; idx < NN * NN; idx += blockDim.x) {
        int i = idx / NN, j = idx % NN;
        float b = tbl[relidx[idx] * HEADS + h];
        int rhi = (cls & 2) ? ((i / 7 < 4) ? 1 : 2) : 0;
        int rwi = (cls & 1) ? ((i % 7 < 4) ? 1 : 2) : 0;
        int rhj = (cls & 2) ? ((j / 7 < 4) ? 1 : 2) : 0;
        int rwj = (cls & 1) ? ((j % 7 < 4) ? 1 : 2) : 0;
        float msk = ((rhi * 3 + rwi) == (rhj * 3 + rwj)) ? 0.f : -100.f;
        g_bias[((cls * HEADS + h) * NN + i) * 52 + j] = b + msk;
    }
}

// =====================================================================
// 128x128x16 SGEMM, 256 threads, split 8x8 microtile (conflict-free LDS),
// double-buffered smem.
//   QKV=true : A = X (gathered), C = g_qkv (ldc=768)
//   QKV=false: A = g_att,        C = OUT (scattered)
// =====================================================================
template<bool QKV>
__global__ __launch_bounds__(256) void gemm128(const float* __restrict__ X,
                                               const float* __restrict__ W,
                                               const float* __restrict__ bias,
                                               float* __restrict__ OUT) {
    __shared__ float As[2][16][132];
    __shared__ float Bs[2][16][132];
    __shared__ int so[128];

    const int n0 = blockIdx.x * 128;
    const int m0 = blockIdx.y * 128;
    const int t  = threadIdx.x;

    if (t < 128) so[t] = src_offset(m0 + t);
    __syncthreads();

    // ---- load mapping ----
    const int r  = t >> 2;            // 0..63
    const int kq = t & 3;             // 0..3

    const float* ap0;
    const float* ap1;
    if (QKV) {
        ap0 = X + so[r]      + kq * 4;
        ap1 = X + so[r + 64] + kq * 4;
    } else {
        ap0 = g_att + (size_t)(m0 + r)      * 256 + kq * 4;
        ap1 = g_att + (size_t)(m0 + r + 64) * 256 + kq * 4;
    }
    const float* bp0 = W + (size_t)(n0 + r)      * CC + kq * 4;
    const float* bp1 = W + (size_t)(n0 + r + 64) * CC + kq * 4;

    // ---- compute mapping: split microtile ----
    // cols {tx4..tx4+3, 64+tx4..}, rows {ty4..ty4+3, 64+ty4..}
    // quarter-warp B-fetch spans exactly one 128B segment -> conflict-free
    const int tx4 = (t & 15) * 4;
    const int ty4 = (t >> 4) * 4;

    float acc[8][8];
#pragma unroll
    for (int i = 0; i < 8; i++)
#pragma unroll
        for (int j = 0; j < 8; j++) acc[i][j] = 0.f;

    // ---- prologue ----
    float4 ra0 = *(const float4*)ap0;
    float4 ra1 = *(const float4*)ap1;
    float4 rb0 = *(const float4*)bp0;
    float4 rb1 = *(const float4*)bp1;

    int buf = 0;
    {
        As[0][kq * 4 + 0][r] = ra0.x; As[0][kq * 4 + 1][r] = ra0.y;
        As[0][kq * 4 + 2][r] = ra0.z; As[0][kq * 4 + 3][r] = ra0.w;
        As[0][kq * 4 + 0][r + 64] = ra1.x; As[0][kq * 4 + 1][r + 64] = ra1.y;
        As[0][kq * 4 + 2][r + 64] = ra1.z; As[0][kq * 4 + 3][r + 64] = ra1.w;
        Bs[0][kq * 4 + 0][r] = rb0.x; Bs[0][kq * 4 + 1][r] = rb0.y;
        Bs[0][kq * 4 + 2][r] = rb0.z; Bs[0][kq * 4 + 3][r] = rb0.w;
        Bs[0][kq * 4 + 0][r + 64] = rb1.x; Bs[0][kq * 4 + 1][r + 64] = rb1.y;
        Bs[0][kq * 4 + 2][r + 64] = rb1.z; Bs[0][kq * 4 + 3][r + 64] = rb1.w;
    }
    __syncthreads();

#pragma unroll 1
    for (int it = 0; it < 16; ++it) {
        if (it < 15) {
            const int k0 = (it + 1) * 16;
            ra0 = *(const float4*)(ap0 + k0);
            ra1 = *(const float4*)(ap1 + k0);
            rb0 = *(const float4*)(bp0 + k0);
            rb1 = *(const float4*)(bp1 + k0);
        }

#pragma unroll
        for (int k = 0; k < 16; k++) {
            float4 av0 = *(const float4*)&As[buf][k][ty4];
            float4 av1 = *(const float4*)&As[buf][k][ty4 + 64];
            float4 bv0 = *(const float4*)&Bs[buf][k][tx4];
            float4 bv1 = *(const float4*)&Bs[buf][k][tx4 + 64];
            float a[8] = {av0.x, av0.y, av0.z, av0.w, av1.x, av1.y, av1.z, av1.w};
            float b[8] = {bv0.x, bv0.y, bv0.z, bv0.w, bv1.x, bv1.y, bv1.z, bv1.w};
#pragma unroll
            for (int i = 0; i < 8; i++)
#pragma unroll
                for (int j = 0; j < 8; j++) acc[i][j] += a[i] * b[j];
        }

        if (it < 15) {
            const int nb = buf ^ 1;
            As[nb][kq * 4 + 0][r] = ra0.x; As[nb][kq * 4 + 1][r] = ra0.y;
            As[nb][kq * 4 + 2][r] = ra0.z; As[nb][kq * 4 + 3][r] = ra0.w;
            As[nb][kq * 4 + 0][r + 64] = ra1.x; As[nb][kq * 4 + 1][r + 64] = ra1.y;
            As[nb][kq * 4 + 2][r + 64] = ra1.z; As[nb][kq * 4 + 3][r + 64] = ra1.w;
            Bs[nb][kq * 4 + 0][r] = rb0.x; Bs[nb][kq * 4 + 1][r] = rb0.y;
            Bs[nb][kq * 4 + 2][r] = rb0.z; Bs[nb][kq * 4 + 3][r] = rb0.w;
            Bs[nb][kq * 4 + 0][r + 64] = rb1.x; Bs[nb][kq * 4 + 1][r + 64] = rb1.y;
            Bs[nb][kq * 4 + 2][r + 64] = rb1.z; Bs[nb][kq * 4 + 3][r + 64] = rb1.w;
            __syncthreads();
            buf = nb;
        }
    }

    // ---- epilogue: rows {m0+ty4+i, m0+64+ty4+i}, cols {n0+tx4, n0+64+tx4} ----
    float4 bb0 = *(const float4*)(bias + n0 + tx4);
    float4 bb1 = *(const float4*)(bias + n0 + 64 + tx4);
#pragma unroll
    for (int i = 0; i < 8; i++) {
        const int mr = (i < 4) ? (ty4 + i) : (64 + ty4 + i - 4);
        float* cp_lo;
        float* cp_hi;
        if (QKV) {
            float* base = g_qkv + (size_t)(m0 + mr) * 768 + n0;
            cp_lo = base + tx4;
            cp_hi = base + 64 + tx4;
        } else {
            float* base = OUT + so[mr] + n0;
            cp_lo = base + tx4;
            cp_hi = base + 64 + tx4;
        }
        float4 o0, o1;
        o0.x = acc[i][0] + bb0.x; o0.y = acc[i][1] + bb0.y;
        o0.z = acc[i][2] + bb0.z; o0.w = acc[i][3] + bb0.w;
        o1.x = acc[i][4] + bb1.x; o1.y = acc[i][5] + bb1.y;
        o1.z = acc[i][6] + bb1.z; o1.w = acc[i][7] + bb1.w;
        *(float4*)cp_lo = o0;
        *(float4*)cp_hi = o1;
    }
}

// =====================================================================
// Kernel 2: windowed attention. One block per (window, head).
// Bias+mask comes precomputed from g_bias (indexed by window class).
// =====================================================================
__global__ __launch_bounds__(256) void attn_kernel() {
    __shared__ float qs[NN * HD];        // [i][d]
    __shared__ float vs[NN * HD];        // [j][d]
    __shared__ float kT[HD * 56];        // [d][j]
    __shared__ float sS[NN * 52];        // scores

    const int w = blockIdx.x >> 3;
    const int h = blockIdx.x & 7;
    const int t = threadIdx.x;

    const int wi = w & 63;
    const int cls = (((wi >> 3) == 7) ? 2 : 0) | (((wi & 7) == 7) ? 1 : 0);
    const float* gb = g_bias + (size_t)((cls * HEADS + h) * NN) * 52;

    const float* base = g_qkv + (size_t)w * NN * 768 + h * HD;
    for (int idx = t; idx < NN * 8; idx += 256) {       // 49 rows x 8 float4
        int n = idx >> 3, dq = idx & 7;
        const float4* p = (const float4*)(base + n * 768 + dq * 4);
        float4 q4 = p[0];       // q at +0
        float4 k4 = p[64];      // k at +256 floats
        float4 v4 = p[128];     // v at +512 floats
        *(float4*)&qs[n * HD + dq * 4] = q4;
        *(float4*)&vs[n * HD + dq * 4] = v4;
        kT[(dq * 4 + 0) * 56 + n] = k4.x;
        kT[(dq * 4 + 1) * 56 + n] = k4.y;
        kT[(dq * 4 + 2) * 56 + n] = k4.z;
        kT[(dq * 4 + 3) * 56 + n] = k4.w;
    }
    __syncthreads();

    // ---- scores: 4 row-groups x 64 j-lanes ----
    const int jg = t & 63, rgp = t >> 6;
    const float scale = 0.17677669529663687f;   // 32^-0.5
    for (int i = rgp; i < NN; i += 4) {
        if (jg < NN) {
            float acc = 0.f;
#pragma unroll
            for (int kk = 0; kk < HD; kk++)
                acc += qs[i * HD + kk] * kT[kk * 56 + jg];
            sS[i * 52 + jg] = acc * scale + __ldg(&gb[i * 52 + jg]);
        }
    }
    __syncthreads();

    // ---- softmax: one warp per row ----
    const int wid = t >> 5, lane = t & 31;
    for (int i = wid; i < NN; i += 8) {
        float e0 = sS[i * 52 + lane];
        float e1 = (lane + 32 < NN) ? sS[i * 52 + lane + 32] : -1e30f;
        float mx = fmaxf(e0, e1);
#pragma unroll
        for (int o = 16; o; o >>= 1) mx = fmaxf(mx, __shfl_xor_sync(0xffffffffu, mx, o));
        e0 = __expf(e0 - mx);
        e1 = (lane + 32 < NN) ? __expf(e1 - mx) : 0.f;
        float sm = e0 + e1;
#pragma unroll
        for (int o = 16; o; o >>= 1) sm += __shfl_xor_sync(0xffffffffu, sm, o);
        float inv = 1.f / sm;
        sS[i * 52 + lane] = e0 * inv;
        if (lane + 32 < NN) sS[i * 52 + lane + 32] = e1 * inv;
    }
    __syncthreads();

    // ---- P @ V: 8 row-groups x 32 d-lanes ----
    const int d = t & 31, ig = t >> 5;
    float* outp = g_att + (size_t)w * NN * 256 + h * HD + d;
    for (int i = ig; i < NN; i += 8) {
        float acc = 0.f;
#pragma unroll
        for (int j = 0; j < NN; j++)
            acc += sS[i * 52 + j] * vs[j * HD + d];
        outp[i * 256] = acc;
    }
}

// =====================================================================
extern "C" void kernel_launch(void* const* d_in, const int* in_sizes, int n_in,
                              void* d_out, int out_size) {
    const float* x     = (const float*)d_in[0];
    const float* qkvw  = (const float*)d_in[1];
    const float* qkvb  = (const float*)d_in[2];
    const float* projw = (const float*)d_in[3];
    const float* projb = (const float*)d_in[4];
    const float* tbl   = (const float*)d_in[5];
    const int*   ridx  = (const int*)d_in[6];
    float* out = (float*)d_out;

    (void)in_sizes; (void)n_in; (void)out_size;

    bias_kernel<<<32, 256>>>(tbl, ridx);
    gemm128<true><<<dim3(6, MTOT / 128), 256>>>(x, qkvw, qkvb, nullptr);
    attn_kernel<<<NWTOT * HEADS, 256>>>();
    gemm128<false><<<dim3(2, MTOT / 128), 256>>>(nullptr, projw, projb, out);
}